// round 15
// baseline (speedup 1.0000x reference)
#include <cuda_runtime.h>
#include <cuda_bf16.h>

// Cascaded 16-tap FIR pair == single 33-tap causal conv for columns i >= 32:
//   y[i] = x[i] + sum_{j=1}^{32} g[j] * x[i-j],  g = [1,h] (*) [1,h_rev]
// Columns [0,32) computed exactly (v-mask aware) by lanes 0-3 on row-start tiles.
//
// ROW-PAIRED fma.rn.f32x2 (R14 core) + contiguous warp streams: each warp
// owns ~28 consecutive 256-col tiles of one row-pair region -> sequential
// DRAM streaming, zero-fill staging only on the rare tir==0 tile (branch,
// not per-op selects). Triple-buffered cp.async, depth-2 prefetch (stage
// tile i+2 while computing tile i) to cover DRAM latency (~2x compute/tile).
// Stage is issued AFTER the per-iter __syncwarp so the 3-buffer WAR is safe
// under intra-warp divergence.
//
// B=256 rows, N=131072 cols, F=16.

#define F       16
#define GT      33
#define THREADS 256
#define WARPS   8
#define WCOLS   256                // output columns per warp-tile (x 2 rows)
#define HALO    32
#define SPAN    (WCOLS + HALO)     // 288 staged columns
#define NCOL    131072
#define NROW    256
#define TPR     (NCOL / WCOLS)     // 512 tiles per row-pair (power of 2)
#define NWT     (TPR * (NROW / 2)) // 65536 warp-tiles
#define NBLK    296                // 2 CTAs per SM
#define NSTREAM (NBLK * WARPS)     // 2368 warp streams
#define QT      (NWT / NSTREAM)    // 27 tiles per stream (base)
#define RT      (NWT % NSTREAM)    // 1600 streams get one extra

// interleaved tile: 36 segments of 8 col-pairs, padded 16->20 floats/segment
#define SEGP    20
#define NSEG    (SPAN / 8)                 // 36
#define BUFW    (NSEG * SEGP)              // 720 floats per buffer
#define WSLOT   (3 * BUFW)                 // triple-buffered, per warp
#define SMEM_DYN (WARPS * WSLOT * 4)       // 69120 B

typedef unsigned long long u64;

#define FMA2(d, a, b, c) \
    asm("fma.rn.f32x2 %0, %1, %2, %3;" : "=l"(d) : "l"(a), "l"(b), "l"(c))
#define PACK2(p, lo, hi) \
    asm("mov.b64 %0, {%1, %2};" : "=l"(p) : "f"(lo), "f"(hi))
#define UNPACK2(lo, hi, p) \
    asm("mov.b64 {%0, %1}, %2;" : "=f"(lo), "=f"(hi) : "l"(p))

__device__ __forceinline__ void cp4(unsigned dst, const float* src, int sz) {
    asm volatile("cp.async.ca.shared.global [%0], [%1], 4, %2;"
                 :: "r"(dst), "l"(src), "r"(sz));
}
__device__ __forceinline__ void cp_commit() {
    asm volatile("cp.async.commit_group;");
}
template <int N> __device__ __forceinline__ void cp_wait() {
    asm volatile("cp.async.wait_group %0;" :: "n"(N));
}

// Stage warp-tile wt interleaved: staged col sc in [0, 288):
// (x0[t0-32+sc], x1[t0-32+sc]) -> float idx 20*(sc>>3) + 2*(sc&7) (+1 row1).
__device__ __forceinline__ void stage_wt(unsigned sb, const float* x,
                                         int wt, int lane)
{
    const int p   = wt >> 9;               // / TPR
    const int tir = wt & (TPR - 1);
    const float* s0 = x + ((size_t)p << 18) + tir * WCOLS - HALO;  // 2p*NCOL
    const float* s1 = s0 + NCOL;
    if (tir != 0) {                        // common path: no predication
#pragma unroll
        for (int k = 0; k < SPAN / 32; k++) {      // 9 iters
            const int sc = lane + 32 * k;
            const unsigned d = sb + ((20 * (sc >> 3) + 2 * (sc & 7)) << 2);
            cp4(d, s0 + sc, 4);
            cp4(d + 4, s1 + sc, 4);
        }
    } else {                               // row start: zero-fill halo
#pragma unroll
        for (int k = 0; k < SPAN / 32; k++) {
            const int sc = lane + 32 * k;
            const int sz = (sc < HALO) ? 0 : 4;
            const float* a = sz ? (s0 + sc) : x;
            const float* b = sz ? (s1 + sc) : x;
            const unsigned d = sb + ((20 * (sc >> 3) + 2 * (sc & 7)) << 2);
            cp4(d, a, sz);
            cp4(d + 4, b, sz);
        }
    }
}

__global__ __launch_bounds__(THREADS, 2)
void fir2_fused(const float* __restrict__ x,
                const float* __restrict__ h,
                float* __restrict__ y)
{
    extern __shared__ float smem[];

    const int tid  = threadIdx.x;
    const int wid  = tid >> 5;
    const int lane = tid & 31;

    float* const wbase = smem + wid * WSLOT;
    const unsigned sbw = (unsigned)__cvta_generic_to_shared(wbase);

    // ---- combined taps: per-thread, packed (g,g) into registers ------------
    float hh[F];
#pragma unroll
    for (int j = 0; j < F; j++) hh[j] = __ldg(h + j);

    u64 tp[32];                                // tp[j-1] = (g[j], g[j])
#pragma unroll
    for (int j = 1; j < GT; j++) {
        float acc = 0.0f;
        const int a0 = (j > F) ? (j - F) : 0;
        const int a1 = (j < F) ? j : F;
#pragma unroll
        for (int a = 0; a <= F; a++) {
            if (a >= a0 && a <= a1) {
                const float ka = (a == 0) ? 1.0f : hh[a - 1];
                const int bb = j - a;
                const float kb = (bb == 0) ? 1.0f : hh[F - bb];
                acc += ka * kb;
            }
        }
        PACK2(tp[j - 1], acc, acc);
    }

    // ---- contiguous stream range -------------------------------------------
    const int S     = blockIdx.x * WARPS + wid;
    const int start = S * QT + ((S < RT) ? S : RT);
    const int cnt   = QT + (S < RT ? 1 : 0);

    // ---- prologue: stage tiles 0 and 1 of this stream ----------------------
    stage_wt(sbw + (0 % 3) * (BUFW * 4), x, start, lane);
    cp_commit();
    stage_wt(sbw + (1 % 3) * (BUFW * 4), x, start + 1, lane);
    cp_commit();

    for (int i = 0; i < cnt; i++) {
        const int wt = start + i;

        cp_wait<1>();                      // tile i's group complete
        __syncwarp();                      // all lanes' groups landed; also
                                           // all lanes done reading buf (i-1)%3
        if (i + 2 < cnt)
            stage_wt(sbw + ((i + 2) % 3) * (BUFW * 4), x, wt + 2, lane);
        cp_commit();                       // always: keep group count aligned

        const int p   = wt >> 9;
        const int tir = wt & (TPR - 1);
        const int t0  = tir * WCOLS;
        const size_t r0off = (size_t)p << 18;          // 2p*NCOL
        const float* sxc = wbase + (i % 3) * BUFW;

        if (!(tir == 0 && lane < 4)) {
            // ---- window: wd[k] = pair at staged col (8*lane + k), k in [0,40)
            u64 wd[40];
#pragma unroll
            for (int s = 0; s < 5; s++) {
                const float* ip = sxc + 20 * (lane + s);
#pragma unroll
                for (int q = 0; q < 4; q++) {
                    const ulonglong2 v =
                        *reinterpret_cast<const ulonglong2*>(ip + 4 * q);
                    wd[8 * s + 2 * q]     = v.x;
                    wd[8 * s + 2 * q + 1] = v.y;
                }
            }

            u64 acc[8];
#pragma unroll
            for (int r = 0; r < 8; r++) acc[r] = wd[32 + r];   // identity tap

#pragma unroll
            for (int j = 1; j < GT; j++) {
#pragma unroll
                for (int r = 0; r < 8; r++)
                    FMA2(acc[r], tp[j - 1], wd[32 + r - j], acc[r]);
            }

            // ---- deinterleave + store both rows ----------------------------
            float o0[8], o1[8];
#pragma unroll
            for (int r = 0; r < 8; r++) UNPACK2(o0[r], o1[r], acc[r]);

            float4* y0 = reinterpret_cast<float4*>(y + r0off + t0 + 8 * lane);
            float4* y1 = reinterpret_cast<float4*>(y + r0off + NCOL + t0 + 8 * lane);
            y0[0] = make_float4(o0[0], o0[1], o0[2], o0[3]);
            y0[1] = make_float4(o0[4], o0[5], o0[6], o0[7]);
            y1[0] = make_float4(o1[0], o1[1], o1[2], o1[3]);
            y1[1] = make_float4(o1[4], o1[5], o1[6], o1[7]);
        } else {
            // ---- exact masked two-stage result, cols [0,32), both rows -----
            // lane 0: row0 zeros; lane 1: row0 compute;
            // lane 2: row1 zeros; lane 3: row1 compute.
            const size_t ro = r0off + (size_t)(lane >> 1) * NCOL;
            if ((lane & 1) == 0) {
                float4* yo = reinterpret_cast<float4*>(y + ro);
#pragma unroll
                for (int q = 0; q < 4; q++)
                    yo[q] = make_float4(0.f, 0.f, 0.f, 0.f);   // y[0..16) = 0
            } else {
                const float* xr = x + ro;
                float xa[32];
#pragma unroll
                for (int cc = 0; cc < 32; cc++) xa[cc] = xr[cc];

                float va[F];               // v[16..31]
#pragma unroll
                for (int tt = 0; tt < F; tt++) {
                    const int k = F + tt;
                    float a2 = xa[k];
#pragma unroll
                    for (int j = 0; j < F; j++)
                        a2 = fmaf(hh[j], xa[k - 1 - j], a2);
                    va[tt] = a2;
                }
                float ya[F];               // y[16..31]
#pragma unroll
                for (int tt = 0; tt < F; tt++) {
                    const int i2 = F + tt;
                    float a2 = va[tt];
#pragma unroll
                    for (int m = 0; m < F; m++) {
                        const int k = i2 - F + m;  // v index; masked if < 16
                        if (k >= F) a2 = fmaf(hh[m], va[k - F], a2);
                    }
                    ya[tt] = a2;
                }
                float4* yo = reinterpret_cast<float4*>(y + ro + F);
#pragma unroll
                for (int q = 0; q < 4; q++)
                    yo[q] = make_float4(ya[4 * q], ya[4 * q + 1],
                                        ya[4 * q + 2], ya[4 * q + 3]);
            }
        }
    }
}

extern "C" void kernel_launch(void* const* d_in, const int* in_sizes, int n_in,
                              void* d_out, int out_size)
{
    const float* x = (const float*)d_in[0];   // (256, 131072) f32
    const float* h = (const float*)d_in[1];   // (1, 16) f32
    float* y = (float*)d_out;                 // (256, 131072) f32

    cudaFuncSetAttribute(fir2_fused,
                         cudaFuncAttributeMaxDynamicSharedMemorySize, SMEM_DYN);
    fir2_fused<<<NBLK, THREADS, SMEM_DYN>>>(x, h, y);
}